// round 7
// baseline (speedup 1.0000x reference)
#include <cuda_runtime.h>

#define HH   256
#define P5   1024
#define NQ   128
#define GRID_MAIN  152   // GB300 SM count
#define BLOCK_MAIN 384   // 12 warps/SM, 3/SMSP; 2 points/thread (f32x2 packed)

typedef unsigned long long u64;

__device__ float g_w2r[HH];
__device__ float g_c;

__device__ __forceinline__ float ex2a(float x) {
    float y; asm("ex2.approx.f32 %0, %1;" : "=f"(y) : "f"(x)); return y;
}
__device__ __forceinline__ u64 pk(float a, float b) {
    u64 r; asm("mov.b64 %0, {%1,%2};" : "=l"(r) : "f"(a), "f"(b)); return r;
}
__device__ __forceinline__ void upk(float& a, float& b, u64 v) {
    asm("mov.b64 {%0,%1}, %2;" : "=f"(a), "=f"(b) : "l"(v));
}
__device__ __forceinline__ u64 fma2(u64 a, u64 b, u64 c) {
    u64 d; asm("fma.rn.f32x2 %0, %1, %2, %3;" : "=l"(d) : "l"(a), "l"(b), "l"(c)); return d;
}
__device__ __forceinline__ u64 mul2(u64 a, u64 b) {
    u64 d; asm("mul.rn.f32x2 %0, %1, %2;" : "=l"(d) : "l"(a), "l"(b)); return d;
}
__device__ __forceinline__ u64 add2(u64 a, u64 b) {
    u64 d; asm("add.rn.f32x2 %0, %1, %2;" : "=l"(d) : "l"(a), "l"(b)); return d;
}
__device__ __forceinline__ float warp_sum(float v) {
    #pragma unroll
    for (int o = 16; o; o >>= 1) v += __shfl_xor_sync(0xffffffffu, v, o);
    return v;
}

// ---------------------------------------------------------------------------
// Kernel 1 (fused setup + w2r): 128 blocks x 256 threads. (unchanged)
// ---------------------------------------------------------------------------
__global__ __launch_bounds__(256)
void w2r_fused_kernel(
    const float* __restrict__ eq,
    const float* __restrict__ q0, const float* __restrict__ q1,
    const float* __restrict__ q2, const float* __restrict__ q3,
    const float* __restrict__ q4,
    const float* __restrict__ Wq0, const float* __restrict__ bq0,
    const float* __restrict__ Wq1, const float* __restrict__ bq1,
    const float* __restrict__ Wq2, const float* __restrict__ bq2,
    const float* __restrict__ Wq3, const float* __restrict__ bq3,
    const float* __restrict__ Wq4, const float* __restrict__ bq4,
    const float* __restrict__ bx2,
    const float* __restrict__ Wx2)
{
    __shared__ float s[5][64];
    __shared__ float t01[16][16];
    __shared__ float t23[16][16];
    __shared__ float partA[5][4], partB[5][4];
    __shared__ float sA[5], sB[5];
    __shared__ float red[8];

    const int tid  = threadIdx.x;
    const int lane = tid & 31;
    const int wrp  = tid >> 5;
    const int h0   = blockIdx.x * 2;

    const float4 wrow0 = reinterpret_cast<const float4*>(Wx2 + h0 * P5)[tid];
    const float4 wrow1 = reinterpret_cast<const float4*>(Wx2 + (h0 + 1) * P5)[tid];

    const float eqv = eq[0];

    if (tid < NQ) {
        const float* qp[5] = {q0, q1, q2, q3, q4};
        #pragma unroll
        for (int i = 0; i < 5; i++) {
            float q = qp[i][tid];
            float y = __expf(-q * q * eqv);
            float a = warp_sum(y * q);
            float b = warp_sum(y);
            if (lane == 0) { partA[i][wrp] = a; partB[i][wrp] = b; }
        }
    }
    __syncthreads();
    if (tid < 5) {
        sA[tid] = partA[tid][0] + partA[tid][1] + partA[tid][2] + partA[tid][3];
        sB[tid] = partB[tid][0] + partB[tid][1] + partB[tid][2] + partB[tid][3];
    }
    __syncthreads();

    if (tid < 64) {
        s[0][tid] = sA[0] * Wq0[tid] + sB[0] * bq0[tid];
        s[1][tid] = sA[1] * Wq1[tid] + sB[1] * bq1[tid];
        s[2][tid] = sA[2] * Wq2[tid] + sB[2] * bq2[tid];
        s[3][tid] = sA[3] * Wq3[tid] + sB[3] * bq3[tid];
        s[4][tid] = sA[4] * Wq4[tid] + sB[4] * bq4[tid];
    }
    __syncthreads();

    {
        int pq = tid >> 4;
        int x  = tid & 15;
        t01[x][pq] = s[0][(pq >> 2) * 16 + x] * s[1][(pq & 3) * 16 + x];
        t23[x][pq] = s[2][(pq >> 2) * 16 + x] * s[3][(pq & 3) * 16 + x];
    }
    __syncthreads();

    const int bd = tid >> 4;
    const int fm = tid & 15;
    float a0 = 0.f, a1 = 0.f, a2 = 0.f, a3 = 0.f;
    #pragma unroll
    for (int x = 0; x < 16; x++) {
        float u = t01[x][bd] * t23[x][fm];
        a0 = fmaf(u, s[4][x],      a0);
        a1 = fmaf(u, s[4][16 + x], a1);
        a2 = fmaf(u, s[4][32 + x], a2);
        a3 = fmaf(u, s[4][48 + x], a3);
    }

    float d0 = wrow0.x * a0 + wrow0.y * a1 + wrow0.z * a2 + wrow0.w * a3;
    float d1 = wrow1.x * a0 + wrow1.y * a1 + wrow1.z * a2 + wrow1.w * a3;
    d0 = warp_sum(d0);
    d1 = warp_sum(d1);
    if (lane == 0) red[wrp] = d0;
    __syncthreads();
    if (tid == 0) {
        float t = 0.f;
        #pragma unroll
        for (int w = 0; w < 8; w++) t += red[w];
        g_w2r[h0] = t;
    }
    __syncthreads();
    if (lane == 0) red[wrp] = d1;
    __syncthreads();
    if (tid == 0) {
        float t = 0.f;
        #pragma unroll
        for (int w = 0; w < 8; w++) t += red[w];
        g_w2r[h0 + 1] = t;
    }

    if (blockIdx.x == 0) {
        float4 bv = reinterpret_cast<const float4*>(bx2)[tid];
        float cp = a0 * bv.x + a1 * bv.y + a2 * bv.z + a3 * bv.w;
        cp = warp_sum(cp);
        __syncthreads();
        if (lane == 0) red[wrp] = cp;
        __syncthreads();
        if (tid == 0) {
            float c = 0.f;
            #pragma unroll
            for (int w = 0; w < 8; w++) c += red[w];
            g_c = c;
        }
    }
}

// ---------------------------------------------------------------------------
// Kernel 2: out[n] = cS - 2 * sum_h w2r[h] / (1 + exp(2*z_h))
//   where z_h = x.W1[:,h]+b1[h], cS = c + sum_h w2r[h]   (tanh = 1 - 2/(1+e))
// e via ex2.approx (1 MUFU, rt8); reciprocal via bit-trick seed (ALU) +
// 2 Newton iterations on the FMA pipe, all f32x2-packed over 2 points/thread.
// Weights pre-duplicated in smem so LDS.128 yields {w,w} pairs directly.
// ---------------------------------------------------------------------------
__global__ __launch_bounds__(BLOCK_MAIN)
void main_kernel(const float* __restrict__ input,
                 const float* __restrict__ Wx1,
                 const float* __restrict__ bx1,
                 float* __restrict__ out, int N)
{
    __shared__ ulonglong2 sWa[HH];   // {Kwx,Kwx},{Kwy,Kwy}
    __shared__ ulonglong2 sWb[HH];   // {Kwz,Kwz},{Kb,Kb}
    __shared__ u64        sRp[HH];   // {w2r,w2r}
    __shared__ float      sred[BLOCK_MAIN / 32];
    __shared__ float      sCS;

    const int tid  = threadIdx.x;
    const int lane = tid & 31;
    const int wrp  = tid >> 5;
    const float K = 2.0f * 1.4426950408889634f;  // 2*log2(e)

    float rv = 0.f;
    if (tid < HH) {
        float wx = Wx1[tid] * K, wy = Wx1[HH + tid] * K;
        float wz = Wx1[2 * HH + tid] * K, wb = bx1[tid] * K;
        ulonglong2 a; a.x = pk(wx, wx); a.y = pk(wy, wy);
        ulonglong2 b; b.x = pk(wz, wz); b.y = pk(wb, wb);
        sWa[tid] = a; sWb[tid] = b;
        rv = g_w2r[tid];
        sRp[tid] = pk(rv, rv);
    }
    // cS = c + sum_h w2r[h]
    float ws = warp_sum(rv);
    if (lane == 0) sred[wrp] = ws;
    __syncthreads();
    if (tid == 0) {
        float S = 0.f;
        #pragma unroll
        for (int w = 0; w < BLOCK_MAIN / 32; w++) S += sred[w];
        sCS = g_c + S;
    }
    __syncthreads();

    const int ppb  = (N + GRID_MAIN - 1) / GRID_MAIN;   // 658 for N=100000
    const int base = blockIdx.x * ppb;
    const int end  = min(base + ppb, N);
    const float cS = sCS;

    const u64 C1  = pk(1.0f, 1.0f);
    const u64 CN1 = pk(-1.0f, -1.0f);
    const u64 C2  = pk(2.0f, 2.0f);
    const unsigned MAGIC = 0x7EF311C3u;

    for (int c0 = base; c0 < end; c0 += 2 * BLOCK_MAIN) {
        const int  n0 = c0 + tid;
        const int  n1 = n0 + BLOCK_MAIN;
        const bool v0 = n0 < end;
        const bool v1 = n1 < end;

        float x00 = 0.f, x01 = 0.f, x02 = 0.f;
        float x10 = 0.f, x11 = 0.f, x12 = 0.f;
        if (v0) { x00 = input[3*n0]; x01 = input[3*n0+1]; x02 = input[3*n0+2]; }
        if (v1) { x10 = input[3*n1]; x11 = input[3*n1+1]; x12 = input[3*n1+2]; }

        const u64 px0 = pk(x00, x10);
        const u64 px1 = pk(x01, x11);
        const u64 px2 = pk(x02, x12);

        u64 acc = 0;  // {0.f, 0.f}

        #pragma unroll 8
        for (int h = 0; h < HH; h++) {
            ulonglong2 wa = sWa[h];          // LDS.128
            ulonglong2 wb = sWb[h];          // LDS.128
            u64 rr = sRp[h];                 // LDS.64

            u64 z = fma2(px0, wa.x, wb.y);   // x0*Kwx + Kb
            z = fma2(px1, wa.y, z);
            z = fma2(px2, wb.x, z);

            float zl, zh; upk(zl, zh, z);
            u64 e = pk(ex2a(zl), ex2a(zh));  // {exp(2z0), exp(2z1)}

            u64 d  = add2(e, C1);            // 1+e
            u64 nd = fma2(e, CN1, CN1);      // -(1+e)

            unsigned dl = (unsigned)d, dh = (unsigned)(d >> 32);
            u64 y = (u64)(MAGIC - dl) | ((u64)(MAGIC - dh) << 32);  // ~1/d seed

            y = mul2(y, fma2(nd, y, C2));    // Newton 1
            y = mul2(y, fma2(nd, y, C2));    // Newton 2

            acc = fma2(y, rr, acc);          // += r * w2r
        }

        float al, ah; upk(al, ah, acc);
        if (v0) out[n0] = fmaf(-2.0f, al, cS);
        if (v1) out[n1] = fmaf(-2.0f, ah, cS);
    }
}

// ---------------------------------------------------------------------------
extern "C" void kernel_launch(void* const* d_in, const int* in_sizes, int n_in,
                              void* d_out, int out_size)
{
    const float* input = (const float*)d_in[0];
    const float* eq    = (const float*)d_in[1];
    const float* q0    = (const float*)d_in[2];
    const float* q1    = (const float*)d_in[3];
    const float* q2    = (const float*)d_in[4];
    const float* q3    = (const float*)d_in[5];
    const float* q4    = (const float*)d_in[6];
    const float* Wx1   = (const float*)d_in[7];
    const float* bx1   = (const float*)d_in[8];
    const float* Wx2   = (const float*)d_in[9];
    const float* bx2   = (const float*)d_in[10];
    const float* Wq0   = (const float*)d_in[11];
    const float* bq0   = (const float*)d_in[12];
    const float* Wq1   = (const float*)d_in[13];
    const float* bq1   = (const float*)d_in[14];
    const float* Wq2   = (const float*)d_in[15];
    const float* bq2   = (const float*)d_in[16];
    const float* Wq3   = (const float*)d_in[17];
    const float* bq3   = (const float*)d_in[18];
    const float* Wq4   = (const float*)d_in[19];
    const float* bq4   = (const float*)d_in[20];

    const int N = in_sizes[0] / 3;

    w2r_fused_kernel<<<HH / 2, 256>>>(eq, q0, q1, q2, q3, q4,
                                      Wq0, bq0, Wq1, bq1, Wq2, bq2,
                                      Wq3, bq3, Wq4, bq4, bx2, Wx2);
    main_kernel<<<GRID_MAIN, BLOCK_MAIN>>>(input, Wx1, bx1, (float*)d_out, N);
}